// round 12
// baseline (speedup 1.0000x reference)
#include <cuda_runtime.h>
#include <cstdint>

// ---------------------------------------------------------------------------
// Contrast loss, fused:
//   a_i = zp1_i/|zp1_i| * (log2e/tau),  b_j = zp2_j/|zp2_j|
//   m[i][j] = 2^(a_i . b_j)
//   loss = LN2*( LAM*sum(lg2 rs) + (1-LAM)*sum(lg2 cs) - sum(a_i.b_i) ) / N
//
// Packed-row trick: g_ap row-pair interleaved {a_{2p,k}, a_{2p+1,k}}, g_bd
// duplicated {b_k, b_k}; one 8-deep fma.f32x2 chain = TWO dots.
//
// Pair kernel (this round): per-WARP cp.async staging — each warp owns an
// 8-column block and a private 4-stage 512B ring; sync is wait_group +
// __syncwarp only (NO CTA barrier in the hot loop). Column sums use a
// 5-shfl value-splitting butterfly instead of 4x4 chains. Row sums in packed
// registers, reduced once per CTA at the end. Zero-padded rows/cols give
// 2^0 = 1, cancelled exactly in the sum initializers.
// ---------------------------------------------------------------------------

#define TAU   0.5f
#define LAM   0.5f
#define EPS   1e-8f
#define LOG2E 1.4426950408889634f
#define LN2   0.6931471805599453f

#define MAXPAD 16384
#define NCHUNKS 16

__device__ __align__(16) float g_ap[MAXPAD * 8];    // row-pair interleaved
__device__ __align__(16) float g_bd[MAXPAD * 16];   // duplicated
__device__ float g_rs[MAXPAD];
__device__ float g_cs[MAXPAD];
__device__ float g_part[3];
__device__ unsigned int g_cnt;

typedef unsigned long long u64;
typedef unsigned int       u32;

__device__ __forceinline__ u32 smem_u32(const void* p) {
    u32 a;
    asm("{ .reg .u64 t; cvta.to.shared.u64 t, %1; cvt.u32.u64 %0, t; }"
        : "=r"(a) : "l"(p));
    return a;
}

__device__ __forceinline__ void cp_async16(u32 saddr, const void* gaddr) {
    asm volatile("cp.async.ca.shared.global [%0], [%1], 16;"
                 :: "r"(saddr), "l"(gaddr) : "memory");
}
__device__ __forceinline__ void cp_commit() {
    asm volatile("cp.async.commit_group;" ::: "memory");
}

__device__ __forceinline__ u64 mul2(u64 a, u64 b) {
    u64 r; asm("mul.rn.f32x2 %0, %1, %2;" : "=l"(r) : "l"(a), "l"(b)); return r;
}
__device__ __forceinline__ u64 fma2(u64 a, u64 b, u64 c) {
    u64 r; asm("fma.rn.f32x2 %0, %1, %2, %3;" : "=l"(r) : "l"(a), "l"(b), "l"(c));
    return r;
}
__device__ __forceinline__ u64 add2(u64 a, u64 b) {
    u64 r; asm("add.rn.f32x2 %0, %1, %2;" : "=l"(r) : "l"(a), "l"(b)); return r;
}

__device__ __forceinline__ float ex2(float x) {
    float r;
    asm("ex2.approx.ftz.f32 %0, %1;" : "=f"(r) : "f"(x));
    return r;
}
__device__ __forceinline__ float lg2(float x) {
    float r;
    asm("lg2.approx.f32 %0, %1;" : "=f"(r) : "f"(x));
    return r;
}

// ------------------------------- K1: projection ----------------------------
__global__ void proj_kernel(const float* __restrict__ z_mp,
                            const float* __restrict__ z_sc,
                            const float* __restrict__ W1,
                            const float* __restrict__ b1,
                            const float* __restrict__ W2,
                            const float* __restrict__ b2,
                            int N, int NpadC, float rs_init, float cs_init) {
    __shared__ float w1s[64], w2s[64], b1s[8], b2s[8];
    int t = threadIdx.x;
    if (t < 64) { w1s[t] = W1[t]; w2s[t] = W2[t]; }
    if (t < 8)  { b1s[t] = b1[t]; b2s[t] = b2[t]; }
    if (blockIdx.x == 0 && t < 3) g_part[t] = 0.0f;
    if (blockIdx.x == 0 && t == 3) g_cnt = 0u;
    __syncthreads();

    int idx = blockIdx.x * blockDim.x + t;
    if (idx >= 2 * NpadC) return;
    int side = (idx >= NpadC) ? 1 : 0;     // 0 = z_mp -> g_ap, 1 = z_sc -> g_bd
    int row  = side ? (idx - NpadC) : idx;

    if (!side) { g_rs[row] = rs_init; g_cs[row] = cs_init; }

    float o[8];
    if (row >= N) {
#pragma unroll
        for (int k = 0; k < 8; k++) o[k] = 0.0f;
    } else {
        const float* z = (side ? z_sc : z_mp) + row * 8;
        float zr[8];
#pragma unroll
        for (int d = 0; d < 8; d++) zr[d] = z[d];

        float h[8];
#pragma unroll
        for (int k = 0; k < 8; k++) {
            float s = b1s[k];
#pragma unroll
            for (int d = 0; d < 8; d++) s = fmaf(zr[d], w1s[k * 8 + d], s);
            h[k] = (s > 0.0f) ? s : (ex2(s * LOG2E) - 1.0f);   // ELU(alpha=1)
        }
        float nn = 0.0f;
#pragma unroll
        for (int j = 0; j < 8; j++) {
            float s = b2s[j];
#pragma unroll
            for (int k = 0; k < 8; k++) s = fmaf(h[k], w2s[j * 8 + k], s);
            o[j] = s;
            nn = fmaf(s, s, nn);
        }
        float scl = (side ? 1.0f : (LOG2E / TAU)) * rsqrtf(nn);
#pragma unroll
        for (int k = 0; k < 8; k++) o[k] *= scl;
    }

    if (!side) {
        // row-pair interleave: g_ap[(row>>1)*16 + 2k + (row&1)]
        float* dst = g_ap + (row >> 1) * 16 + (row & 1);
#pragma unroll
        for (int k = 0; k < 8; k++) dst[2 * k] = o[k];
    } else {
        // duplicate: g_bd[row*16 + 2k + {0,1}]
        float* dst = g_bd + row * 16;
#pragma unroll
        for (int k = 0; k < 8; k++) { dst[2 * k] = o[k]; dst[2 * k + 1] = o[k]; }
    }
}

// ------------------------------- K2: pairwise ------------------------------
// grid: (nRowBlocks, NCHUNKS). CTA: 256 threads = 8 warps.
// Warp w owns columns [j0 + w*8, j0 + w*8 + 8) each step, staged in a
// PRIVATE 4-stage 512B smem ring via cp.async (wait_group + __syncwarp only).
// lane = rg(bits 0-3) + half(bit 4): thread computes rows rg*4..+3 (2 packed
// pairs, fixed) x cols cbase..cbase+3 where cbase = w*8 + half*4.
__global__ __launch_bounds__(256, 4) void pair_kernel(int nsteps) {
    __shared__ __align__(16) float wbuf[8][4][128];   // [warp][stage][512B]
    __shared__ float red[64][17];

    const int tid  = threadIdx.x;
    const int lane = tid & 31;
    const int w    = tid >> 5;
    const int rg   = lane & 15;
    const int half = lane >> 4;
    const int bit3 = (lane >> 3) & 1;
    const int bit2 = (lane >> 2) & 1;

    const int row0   = blockIdx.x * 64 + rg * 4;
    const int jbase0 = blockIdx.y * (nsteps * 64);
    const int jw     = jbase0 + w * 8;        // warp's first column, step 0

    // a: two packed row-pairs {a_{r0,k}, a_{r1,k}}, k=0..7 each
    const u64* gap = reinterpret_cast<const u64*>(g_ap);
    u64 a2[2][8];
#pragma unroll
    for (int rp = 0; rp < 2; rp++) {
        const u64* src = gap + (size_t)(row0 / 2 + rp) * 8;
#pragma unroll
        for (int k = 0; k < 8; k++) a2[rp][k] = src[k];
    }

    const u32 sbase = smem_u32(&wbuf[w][0][0]) + lane * 16;
    const float* gbp = g_bd + (size_t)jw * 16 + lane * 4;

    // prologue: prefetch up to 3 stages (512B per warp, 16B/lane)
    const int npre = (nsteps < 3) ? nsteps : 3;
    for (int s = 0; s < npre; ++s) {
        cp_async16(sbase + s * 512, gbp + s * 1024);   // step stride = 64 cols
        cp_commit();
    }

    u64 rowacc2[2] = {0ull, 0ull};   // packed {sum_r0, sum_r1} per row-pair

    for (int ts = 0; ts < nsteps; ++ts) {
        const int rem = nsteps - ts;
        if (rem >= 3)      asm volatile("cp.async.wait_group 2;" ::: "memory");
        else if (rem == 2) asm volatile("cp.async.wait_group 1;" ::: "memory");
        else               asm volatile("cp.async.wait_group 0;" ::: "memory");
        __syncwarp();
        if (ts + 3 < nsteps) {
            cp_async16(sbase + ((ts + 3) & 3) * 512, gbp + (ts + 3) * 1024);
            cp_commit();
        }

        const u64* bb = reinterpret_cast<const u64*>(&wbuf[w][ts & 3][0]);
        const int cbase = jw + ts * 64 + half * 4;
        float cacc[4];
#pragma unroll
        for (int c = 0; c < 4; c++) {
            const u64* bcol = bb + (half * 4 + c) * 8;
            u64 q0 = bcol[0], q1 = bcol[1], q2 = bcol[2], q3 = bcol[3];
            u64 d0 = mul2(a2[0][0], q0);
            u64 d1 = mul2(a2[1][0], q0);
            d0 = fma2(a2[0][1], q1, d0);  d1 = fma2(a2[1][1], q1, d1);
            d0 = fma2(a2[0][2], q2, d0);  d1 = fma2(a2[1][2], q2, d1);
            d0 = fma2(a2[0][3], q3, d0);  d1 = fma2(a2[1][3], q3, d1);
            q0 = bcol[4]; q1 = bcol[5]; q2 = bcol[6]; q3 = bcol[7];
            d0 = fma2(a2[0][4], q0, d0);  d1 = fma2(a2[1][4], q0, d1);
            d0 = fma2(a2[0][5], q1, d0);  d1 = fma2(a2[1][5], q1, d1);
            d0 = fma2(a2[0][6], q2, d0);  d1 = fma2(a2[1][6], q2, d1);
            d0 = fma2(a2[0][7], q3, d0);  d1 = fma2(a2[1][7], q3, d1);

            // each half of d0/d1 is a complete dot -> exponentiate per half
            float e00, e01, e10, e11;
            asm("mov.b64 {%0, %1}, %2;" : "=f"(e00), "=f"(e01) : "l"(d0));
            asm("mov.b64 {%0, %1}, %2;" : "=f"(e10), "=f"(e11) : "l"(d1));
            e00 = ex2(e00); e01 = ex2(e01); e10 = ex2(e10); e11 = ex2(e11);
            u64 e2a, e2b;
            asm("mov.b64 %0, {%1, %2};" : "=l"(e2a) : "f"(e00), "f"(e01));
            asm("mov.b64 %0, {%1, %2};" : "=l"(e2b) : "f"(e10), "f"(e11));
            rowacc2[0] = add2(rowacc2[0], e2a);
            rowacc2[1] = add2(rowacc2[1], e2b);
            cacc[c] = (e00 + e01) + (e10 + e11);
        }

        // value-splitting butterfly: 4 column sums over 16 rg-lanes, 5 shfls.
        // level xor8 (split 4 -> 2): bit3==0 keeps c0,c1; bit3==1 keeps c2,c3
        float s0 = bit3 ? cacc[0] : cacc[2];
        s0 = __shfl_xor_sync(0xffffffffu, s0, 8);
        float S0 = (bit3 ? cacc[2] : cacc[0]) + s0;
        float s1 = bit3 ? cacc[1] : cacc[3];
        s1 = __shfl_xor_sync(0xffffffffu, s1, 8);
        float S1 = (bit3 ? cacc[3] : cacc[1]) + s1;
        // level xor4 (split 2 -> 1): bit2==0 keeps S0-type; bit2==1 keeps S1
        float s2 = bit2 ? S0 : S1;
        s2 = __shfl_xor_sync(0xffffffffu, s2, 4);
        float T = (bit2 ? S1 : S0) + s2;
        // plain levels xor2, xor1
        T += __shfl_xor_sync(0xffffffffu, T, 2);
        T += __shfl_xor_sync(0xffffffffu, T, 1);
        // lane holds sum for column cbase + (bit3*2 + bit2)
        if ((lane & 3) == 0) atomicAdd(&g_cs[cbase + bit3 * 2 + bit2], T);
    }

    // unpack packed row sums -> 4 scalar rows, reduce over 16 column-owners
    float ra[4];
    asm("mov.b64 {%0, %1}, %2;" : "=f"(ra[0]), "=f"(ra[1]) : "l"(rowacc2[0]));
    asm("mov.b64 {%0, %1}, %2;" : "=f"(ra[2]), "=f"(ra[3]) : "l"(rowacc2[1]));
    const int cown = tid >> 4;   // w*2 + half
#pragma unroll
    for (int r = 0; r < 4; r++) red[rg * 4 + r][cown] = ra[r];
    __syncthreads();
    if (tid < 64) {
        float s = 0.0f;
#pragma unroll
        for (int q = 0; q < 16; q++) s += red[tid][q];
        atomicAdd(&g_rs[blockIdx.x * 64 + tid], s);
    }
}

// ------------------------------- K3: partial + fused combine ---------------
__global__ void partial_kernel(float* __restrict__ out, int N, int nblocks) {
    __shared__ float sh0[256], sh1[256], sh2[256];
    __shared__ bool last;
    const int t = threadIdx.x;
    const int i = blockIdx.x * 256 + t;
    float lr = 0.f, lc = 0.f, dd = 0.f;
    if (i < N) {
        lr = lg2(g_rs[i]);
        lc = lg2(g_cs[i]);
        const float* a = g_ap + (i >> 1) * 16 + (i & 1);
        const float* b = g_bd + i * 16;
        float d = 0.f;
#pragma unroll
        for (int k = 0; k < 8; k++) d = fmaf(a[2 * k], b[2 * k], d);
        dd = d;   // log2-domain diag logit
    }
    sh0[t] = lr; sh1[t] = lc; sh2[t] = dd;
    __syncthreads();
    for (int s = 128; s > 0; s >>= 1) {
        if (t < s) { sh0[t] += sh0[t + s]; sh1[t] += sh1[t + s]; sh2[t] += sh2[t + s]; }
        __syncthreads();
    }
    if (t == 0) {
        atomicAdd(&g_part[0], sh0[0]);
        atomicAdd(&g_part[1], sh1[0]);
        atomicAdd(&g_part[2], sh2[0]);
        __threadfence();
        unsigned int ticket = atomicAdd(&g_cnt, 1u);
        last = (ticket == (unsigned int)(nblocks - 1));
    }
    __syncthreads();
    if (last && t == 0) {
        float p0 = atomicAdd(&g_part[0], 0.0f);
        float p1 = atomicAdd(&g_part[1], 0.0f);
        float p2 = atomicAdd(&g_part[2], 0.0f);
        out[0] = LN2 * (LAM * p0 + (1.0f - LAM) * p1 - p2) / (float)N;
    }
}

// ------------------------------- launch -------------------------------------
extern "C" void kernel_launch(void* const* d_in, const int* in_sizes, int n_in,
                              void* d_out, int out_size) {
    const float* z_mp = (const float*)d_in[0];
    const float* z_sc = (const float*)d_in[1];
    const float* W1   = (const float*)d_in[2];
    const float* b1   = (const float*)d_in[3];
    const float* W2   = (const float*)d_in[4];
    const float* b2   = (const float*)d_in[5];
    float* out = (float*)d_out;

    const int N = in_sizes[0] / 8;

    const int RB = (N + 63) / 64;                              // row blocks
    const int colsPerChunk = ((N + NCHUNKS * 64 - 1) / (NCHUNKS * 64)) * 64;
    const int NpadC = NCHUNKS * colsPerChunk;                  // padded columns
    const int NpadR = RB * 64;                                 // padded rows
    // padded (zero) vectors contribute 2^0 = 1 per pair -> cancel exactly
    const float rs_init = EPS - (float)(NpadC - N);
    const float cs_init = EPS - (float)(NpadR - N);

    const int pthreads = 2 * NpadC;
    proj_kernel<<<(pthreads + 255) / 256, 256>>>(z_mp, z_sc, W1, b1, W2, b2,
                                                 N, NpadC, rs_init, cs_init);

    dim3 grid(RB, NCHUNKS);
    pair_kernel<<<grid, 256>>>(colsPerChunk / 64);

    const int nblocks = (N + 255) / 256;
    partial_kernel<<<nblocks, 256>>>(out, N, nblocks);
}

// round 13
// speedup vs baseline: 1.5744x; 1.5744x over previous
#include <cuda_runtime.h>
#include <cstdint>

// ---------------------------------------------------------------------------
// Contrast loss, fused:
//   a_i = zp1_i/|zp1_i| * (log2e/tau),  b_j = zp2_j/|zp2_j|
//   m[i][j] = 2^(a_i . b_j)
//   loss = LN2*( LAM*sum(lg2 rs) + (1-LAM)*sum(lg2 cs) - sum(a_i.b_i) ) / N
//
// Packed-row trick: g_ap row-pair interleaved {a_{2p,k}, a_{2p+1,k}}, g_bd
// duplicated {b_k, b_k}; one 8-deep fma.f32x2 chain = TWO dots.
//
// Pair kernel = R11 skeleton (CTA-wide 4-stage cp.async staging, ONE barrier
// per step) with MIO reductions: LDS.128 column loads (16 instead of 32 LDS
// per thread-step) and a 5-shfl value-splitting butterfly for the column
// reduction (instead of 4x4 = 16 shfls). Zero-padded rows/cols contribute
// 2^0 = 1 each, cancelled exactly in the sum initializers.
// ---------------------------------------------------------------------------

#define TAU   0.5f
#define LAM   0.5f
#define EPS   1e-8f
#define LOG2E 1.4426950408889634f
#define LN2   0.6931471805599453f

#define MAXPAD 16384
#define NCHUNKS 16

__device__ __align__(16) float g_ap[MAXPAD * 8];    // row-pair interleaved
__device__ __align__(16) float g_bd[MAXPAD * 16];   // duplicated
__device__ float g_rs[MAXPAD];
__device__ float g_cs[MAXPAD];
__device__ float g_part[3];
__device__ unsigned int g_cnt;

typedef unsigned long long u64;
typedef unsigned int       u32;

__device__ __forceinline__ u32 smem_u32(const void* p) {
    u32 a;
    asm("{ .reg .u64 t; cvta.to.shared.u64 t, %1; cvt.u32.u64 %0, t; }"
        : "=r"(a) : "l"(p));
    return a;
}

__device__ __forceinline__ void cp_async16(u32 saddr, const void* gaddr) {
    asm volatile("cp.async.ca.shared.global [%0], [%1], 16;"
                 :: "r"(saddr), "l"(gaddr) : "memory");
}
__device__ __forceinline__ void cp_commit() {
    asm volatile("cp.async.commit_group;" ::: "memory");
}

__device__ __forceinline__ u64 mul2(u64 a, u64 b) {
    u64 r; asm("mul.rn.f32x2 %0, %1, %2;" : "=l"(r) : "l"(a), "l"(b)); return r;
}
__device__ __forceinline__ u64 fma2(u64 a, u64 b, u64 c) {
    u64 r; asm("fma.rn.f32x2 %0, %1, %2, %3;" : "=l"(r) : "l"(a), "l"(b), "l"(c));
    return r;
}
__device__ __forceinline__ u64 add2(u64 a, u64 b) {
    u64 r; asm("add.rn.f32x2 %0, %1, %2;" : "=l"(r) : "l"(a), "l"(b)); return r;
}

__device__ __forceinline__ float ex2(float x) {
    float r;
    asm("ex2.approx.ftz.f32 %0, %1;" : "=f"(r) : "f"(x));
    return r;
}
__device__ __forceinline__ float lg2(float x) {
    float r;
    asm("lg2.approx.f32 %0, %1;" : "=f"(r) : "f"(x));
    return r;
}

// ------------------------------- K1: projection ----------------------------
__global__ void proj_kernel(const float* __restrict__ z_mp,
                            const float* __restrict__ z_sc,
                            const float* __restrict__ W1,
                            const float* __restrict__ b1,
                            const float* __restrict__ W2,
                            const float* __restrict__ b2,
                            int N, int NpadC, float rs_init, float cs_init) {
    __shared__ float w1s[64], w2s[64], b1s[8], b2s[8];
    int t = threadIdx.x;
    if (t < 64) { w1s[t] = W1[t]; w2s[t] = W2[t]; }
    if (t < 8)  { b1s[t] = b1[t]; b2s[t] = b2[t]; }
    if (blockIdx.x == 0 && t < 3) g_part[t] = 0.0f;
    if (blockIdx.x == 0 && t == 3) g_cnt = 0u;
    __syncthreads();

    int idx = blockIdx.x * blockDim.x + t;
    if (idx >= 2 * NpadC) return;
    int side = (idx >= NpadC) ? 1 : 0;     // 0 = z_mp -> g_ap, 1 = z_sc -> g_bd
    int row  = side ? (idx - NpadC) : idx;

    if (!side) { g_rs[row] = rs_init; g_cs[row] = cs_init; }

    float o[8];
    if (row >= N) {
#pragma unroll
        for (int k = 0; k < 8; k++) o[k] = 0.0f;
    } else {
        const float* z = (side ? z_sc : z_mp) + row * 8;
        float zr[8];
#pragma unroll
        for (int d = 0; d < 8; d++) zr[d] = z[d];

        float h[8];
#pragma unroll
        for (int k = 0; k < 8; k++) {
            float s = b1s[k];
#pragma unroll
            for (int d = 0; d < 8; d++) s = fmaf(zr[d], w1s[k * 8 + d], s);
            h[k] = (s > 0.0f) ? s : (ex2(s * LOG2E) - 1.0f);   // ELU(alpha=1)
        }
        float nn = 0.0f;
#pragma unroll
        for (int j = 0; j < 8; j++) {
            float s = b2s[j];
#pragma unroll
            for (int k = 0; k < 8; k++) s = fmaf(h[k], w2s[j * 8 + k], s);
            o[j] = s;
            nn = fmaf(s, s, nn);
        }
        float scl = (side ? 1.0f : (LOG2E / TAU)) * rsqrtf(nn);
#pragma unroll
        for (int k = 0; k < 8; k++) o[k] *= scl;
    }

    if (!side) {
        // row-pair interleave: g_ap[(row>>1)*16 + 2k + (row&1)]
        float* dst = g_ap + (row >> 1) * 16 + (row & 1);
#pragma unroll
        for (int k = 0; k < 8; k++) dst[2 * k] = o[k];
    } else {
        // duplicate: g_bd[row*16 + 2k + {0,1}]
        float* dst = g_bd + row * 16;
#pragma unroll
        for (int k = 0; k < 8; k++) { dst[2 * k] = o[k]; dst[2 * k + 1] = o[k]; }
    }
}

// ------------------------------- K2: pairwise ------------------------------
// grid: (nRowBlocks, NCHUNKS). CTA: 256 threads = 16 rowgroups x 16 colgroups.
// Thread: 4 fixed rows (2 packed row-pairs, regs) x 4 cols/step from SMEM.
// b tiles: 64 cols x 64B(dup) = 4KB, 4-stage cp.async, one barrier per step.
__global__ __launch_bounds__(256, 4) void pair_kernel(int nsteps) {
    __shared__ __align__(16) float bbuf[4][64 * 16];
    __shared__ float red[64][17];

    const int tid  = threadIdx.x;
    const int lane = tid & 31;
    const int rg   = tid & 15;
    const int cg   = tid >> 4;
    const int bit3 = (lane >> 3) & 1;
    const int bit2 = (lane >> 2) & 1;
    const int row0   = blockIdx.x * 64 + rg * 4;
    const int jbase0 = blockIdx.y * (nsteps * 64);

    // a: two packed row-pairs {a_{r0,k}, a_{r1,k}}, k=0..7 each
    const u64* gap = reinterpret_cast<const u64*>(g_ap);
    u64 a2[2][8];
#pragma unroll
    for (int rp = 0; rp < 2; rp++) {
        const u64* src = gap + (size_t)(row0 / 2 + rp) * 8;
#pragma unroll
        for (int k = 0; k < 8; k++) a2[rp][k] = src[k];
    }

    const u32 sbase = smem_u32(&bbuf[0][0]) + tid * 16;
    const float* gbp = g_bd + (size_t)jbase0 * 16 + tid * 4;

    // prologue: prefetch up to 3 tiles (4KB each, 16B/thread)
    const int npre = (nsteps < 3) ? nsteps : 3;
    for (int s = 0; s < npre; ++s) {
        cp_async16(sbase + s * 4096, gbp + s * 1024);
        cp_commit();
    }

    u64 rowacc2[2] = {0ull, 0ull};   // packed {sum_r0, sum_r1} per row-pair

    for (int ts = 0; ts < nsteps; ++ts) {
        const int rem = nsteps - ts;
        if (rem >= 3)      asm volatile("cp.async.wait_group 2;" ::: "memory");
        else if (rem == 2) asm volatile("cp.async.wait_group 1;" ::: "memory");
        else               asm volatile("cp.async.wait_group 0;" ::: "memory");
        __syncthreads();
        if (ts + 3 < nsteps) {
            cp_async16(sbase + ((ts + 3) & 3) * 4096, gbp + (ts + 3) * 1024);
            cp_commit();
        }

        const ulonglong2* bb =
            reinterpret_cast<const ulonglong2*>(&bbuf[ts & 3][0]);
        const int j0 = jbase0 + ts * 64;
        float cacc[4];
#pragma unroll
        for (int c = 0; c < 4; c++) {
            const int lc = cg * 4 + c;
            const ulonglong2* bcol = bb + lc * 4;   // 4 x 16B = one column
            ulonglong2 p0 = bcol[0];
            ulonglong2 p1 = bcol[1];
            u64 d0 = mul2(a2[0][0], p0.x);
            u64 d1 = mul2(a2[1][0], p0.x);
            d0 = fma2(a2[0][1], p0.y, d0);  d1 = fma2(a2[1][1], p0.y, d1);
            d0 = fma2(a2[0][2], p1.x, d0);  d1 = fma2(a2[1][2], p1.x, d1);
            d0 = fma2(a2[0][3], p1.y, d0);  d1 = fma2(a2[1][3], p1.y, d1);
            ulonglong2 p2 = bcol[2];
            ulonglong2 p3 = bcol[3];
            d0 = fma2(a2[0][4], p2.x, d0);  d1 = fma2(a2[1][4], p2.x, d1);
            d0 = fma2(a2[0][5], p2.y, d0);  d1 = fma2(a2[1][5], p2.y, d1);
            d0 = fma2(a2[0][6], p3.x, d0);  d1 = fma2(a2[1][6], p3.x, d1);
            d0 = fma2(a2[0][7], p3.y, d0);  d1 = fma2(a2[1][7], p3.y, d1);

            // each half of d0/d1 is a complete dot -> exponentiate per half
            float e00, e01, e10, e11;
            asm("mov.b64 {%0, %1}, %2;" : "=f"(e00), "=f"(e01) : "l"(d0));
            asm("mov.b64 {%0, %1}, %2;" : "=f"(e10), "=f"(e11) : "l"(d1));
            e00 = ex2(e00); e01 = ex2(e01); e10 = ex2(e10); e11 = ex2(e11);
            u64 e2a, e2b;
            asm("mov.b64 %0, {%1, %2};" : "=l"(e2a) : "f"(e00), "f"(e01));
            asm("mov.b64 %0, {%1, %2};" : "=l"(e2b) : "f"(e10), "f"(e11));
            rowacc2[0] = add2(rowacc2[0], e2a);
            rowacc2[1] = add2(rowacc2[1], e2b);
            u64 ecs = add2(e2a, e2b);
            float cl, ch;
            asm("mov.b64 {%0, %1}, %2;" : "=f"(cl), "=f"(ch) : "l"(ecs));
            cacc[c] = cl + ch;
        }

        // value-splitting butterfly over the 16 rg-lanes: 5 shfls total.
        // level xor8: bit3==0 accumulates c0/c1, bit3==1 accumulates c2/c3
        float s0 = bit3 ? cacc[0] : cacc[2];
        s0 = __shfl_xor_sync(0xffffffffu, s0, 8);
        float S0 = (bit3 ? cacc[2] : cacc[0]) + s0;
        float s1 = bit3 ? cacc[1] : cacc[3];
        s1 = __shfl_xor_sync(0xffffffffu, s1, 8);
        float S1 = (bit3 ? cacc[3] : cacc[1]) + s1;
        // level xor4: bit2==0 keeps S0-type, bit2==1 keeps S1-type
        float s2 = bit2 ? S0 : S1;
        s2 = __shfl_xor_sync(0xffffffffu, s2, 4);
        float T = (bit2 ? S1 : S0) + s2;
        // plain levels xor2, xor1 (sum over lane bits 1:0)
        T += __shfl_xor_sync(0xffffffffu, T, 2);
        T += __shfl_xor_sync(0xffffffffu, T, 1);
        // lane (bits1:0 == 0) holds the sum for column cg*4 + bit3*2 + bit2
        if ((lane & 3) == 0)
            atomicAdd(&g_cs[j0 + cg * 4 + bit3 * 2 + bit2], T);
    }

    // unpack packed row sums -> 4 scalar rows, reduce over 16 colgroups
    float ra[4];
    asm("mov.b64 {%0, %1}, %2;" : "=f"(ra[0]), "=f"(ra[1]) : "l"(rowacc2[0]));
    asm("mov.b64 {%0, %1}, %2;" : "=f"(ra[2]), "=f"(ra[3]) : "l"(rowacc2[1]));
#pragma unroll
    for (int r = 0; r < 4; r++) red[rg * 4 + r][cg] = ra[r];
    __syncthreads();
    if (tid < 64) {
        float s = 0.0f;
#pragma unroll
        for (int q = 0; q < 16; q++) s += red[tid][q];
        atomicAdd(&g_rs[blockIdx.x * 64 + tid], s);
    }
}

// ------------------------------- K3: partial + fused combine ---------------
__global__ void partial_kernel(float* __restrict__ out, int N, int nblocks) {
    __shared__ float sh0[256], sh1[256], sh2[256];
    __shared__ bool last;
    const int t = threadIdx.x;
    const int i = blockIdx.x * 256 + t;
    float lr = 0.f, lc = 0.f, dd = 0.f;
    if (i < N) {
        lr = lg2(g_rs[i]);
        lc = lg2(g_cs[i]);
        const float* a = g_ap + (i >> 1) * 16 + (i & 1);
        const float* b = g_bd + i * 16;
        float d = 0.f;
#pragma unroll
        for (int k = 0; k < 8; k++) d = fmaf(a[2 * k], b[2 * k], d);
        dd = d;   // log2-domain diag logit
    }
    sh0[t] = lr; sh1[t] = lc; sh2[t] = dd;
    __syncthreads();
    for (int s = 128; s > 0; s >>= 1) {
        if (t < s) { sh0[t] += sh0[t + s]; sh1[t] += sh1[t + s]; sh2[t] += sh2[t + s]; }
        __syncthreads();
    }
    if (t == 0) {
        atomicAdd(&g_part[0], sh0[0]);
        atomicAdd(&g_part[1], sh1[0]);
        atomicAdd(&g_part[2], sh2[0]);
        __threadfence();
        unsigned int ticket = atomicAdd(&g_cnt, 1u);
        last = (ticket == (unsigned int)(nblocks - 1));
    }
    __syncthreads();
    if (last && t == 0) {
        float p0 = atomicAdd(&g_part[0], 0.0f);
        float p1 = atomicAdd(&g_part[1], 0.0f);
        float p2 = atomicAdd(&g_part[2], 0.0f);
        out[0] = LN2 * (LAM * p0 + (1.0f - LAM) * p1 - p2) / (float)N;
    }
}

// ------------------------------- launch -------------------------------------
extern "C" void kernel_launch(void* const* d_in, const int* in_sizes, int n_in,
                              void* d_out, int out_size) {
    const float* z_mp = (const float*)d_in[0];
    const float* z_sc = (const float*)d_in[1];
    const float* W1   = (const float*)d_in[2];
    const float* b1   = (const float*)d_in[3];
    const float* W2   = (const float*)d_in[4];
    const float* b2   = (const float*)d_in[5];
    float* out = (float*)d_out;

    const int N = in_sizes[0] / 8;

    const int RB = (N + 63) / 64;                              // row blocks
    const int colsPerChunk = ((N + NCHUNKS * 64 - 1) / (NCHUNKS * 64)) * 64;
    const int NpadC = NCHUNKS * colsPerChunk;                  // padded columns
    const int NpadR = RB * 64;                                 // padded rows
    // padded (zero) vectors contribute 2^0 = 1 per pair -> cancel exactly
    const float rs_init = EPS - (float)(NpadC - N);
    const float cs_init = EPS - (float)(NpadR - N);

    const int pthreads = 2 * NpadC;
    proj_kernel<<<(pthreads + 255) / 256, 256>>>(z_mp, z_sc, W1, b1, W2, b2,
                                                 N, NpadC, rs_init, cs_init);

    dim3 grid(RB, NCHUNKS);
    pair_kernel<<<grid, 256>>>(colsPerChunk / 64);

    const int nblocks = (N + 255) / 256;
    partial_kernel<<<nblocks, 256>>>(out, N, nblocks);
}